// round 1
// baseline (speedup 1.0000x reference)
#include <cuda_runtime.h>
#include <cstddef>

// Block-diagonal batched GEMM:
//   out[start_g + r, :] = sum_h M_g[r,h] * x[start_g + h, :]   (N = 512*21 = 10752 cols)
// Group sizes are compile-time constants; mat pointers passed by value.

#define NGROUPS 15
#define NCOLS   10752   // 512 * 21

__device__ __constant__ int d_gsize[NGROUPS]  = {64,128,256,96,160,224,192,288,320,112,80,48,32,16,32};
__device__ __constant__ int d_gstart[NGROUPS] = {0,64,192,448,544,704,928,1120,1408,1728,1840,1920,1968,2000,2016};

struct MatPtrs { const float* p[NGROUPS]; };

// Tiling: BM x BN output tile per block, BK k-slab. 256 threads, each computes 2x8.
#define BM 32
#define BN 128
#define BK 32

__global__ __launch_bounds__(256, 6)
void bdiag_gemm_kernel(const float* __restrict__ x, float* __restrict__ out, MatPtrs mats)
{
    const int g   = blockIdx.z;
    const int K   = d_gsize[g];
    const int row0 = blockIdx.y * BM;
    if (row0 >= K) return;                      // padded row tiles for small groups
    const int col0 = blockIdx.x * BN;           // NCOLS % BN == 0 (10752/128 = 84)

    const float* __restrict__ M = mats.p[g];
    const float* __restrict__ X = x   + (size_t)d_gstart[g] * NCOLS;
    float*       __restrict__ O = out + (size_t)d_gstart[g] * NCOLS;

    __shared__ float As[BK][BM + 1];   // [k][m], padded -> conflict-free transposed store
    __shared__ float Bs[BK][BN];       // [k][n]

    const int tid = threadIdx.x;
    const int tx  = tid & 15;          // 16 column groups
    const int ty  = tid >> 4;          // 16 row groups
    const int m0  = ty * 2;            // 2 output rows per thread
    const int na  = tx * 4;            // first  float4 column block
    const int nb  = tx * 4 + 64;       // second float4 column block (conflict-free banks)

    float acc[2][8];
    #pragma unroll
    for (int i = 0; i < 2; i++)
        #pragma unroll
        for (int j = 0; j < 8; j++) acc[i][j] = 0.0f;

    for (int kt = 0; kt < K; kt += BK) {
        // ---- load A tile (BM x BK = 1024 elems), store transposed As[k][m]
        #pragma unroll
        for (int e = 0; e < 4; e++) {
            int idx = tid + e * 256;
            int k = idx & 31;          // consecutive threads -> consecutive k (coalesced)
            int m = idx >> 5;
            int gr = row0 + m;
            int gk = kt + k;
            As[k][m] = (gr < K && gk < K) ? M[(size_t)gr * K + gk] : 0.0f;
        }
        // ---- load B tile (BK x BN = 4096 floats) as float4, coalesced
        #pragma unroll
        for (int e = 0; e < 4; e++) {
            int v  = tid + e * 256;    // 0..1023 float4 slots
            int k  = v >> 5;           // 32 float4 per row
            int c4 = v & 31;
            int gk = kt + k;
            float4 val;
            if (gk < K)
                val = *reinterpret_cast<const float4*>(X + (size_t)gk * NCOLS + col0 + c4 * 4);
            else
                val = make_float4(0.f, 0.f, 0.f, 0.f);
            *reinterpret_cast<float4*>(&Bs[k][c4 * 4]) = val;
        }
        __syncthreads();

        // ---- FFMA core: 16 FMAs per thread per k
        #pragma unroll
        for (int k = 0; k < BK; k++) {
            float a0 = As[k][m0];
            float a1 = As[k][m0 + 1];
            float4 b0 = *reinterpret_cast<const float4*>(&Bs[k][na]);
            float4 b1 = *reinterpret_cast<const float4*>(&Bs[k][nb]);
            float bv[8] = {b0.x, b0.y, b0.z, b0.w, b1.x, b1.y, b1.z, b1.w};
            #pragma unroll
            for (int j = 0; j < 8; j++) {
                acc[0][j] += a0 * bv[j];
                acc[1][j] += a1 * bv[j];
            }
        }
        __syncthreads();
    }

    // ---- store (two float4 per row per thread)
    #pragma unroll
    for (int i = 0; i < 2; i++) {
        int gr = row0 + m0 + i;
        if (gr < K) {
            float* dst = O + (size_t)gr * NCOLS + col0;
            *reinterpret_cast<float4*>(dst + na) =
                make_float4(acc[i][0], acc[i][1], acc[i][2], acc[i][3]);
            *reinterpret_cast<float4*>(dst + nb) =
                make_float4(acc[i][4], acc[i][5], acc[i][6], acc[i][7]);
        }
    }
}

extern "C" void kernel_launch(void* const* d_in, const int* in_sizes, int n_in,
                              void* d_out, int out_size)
{
    const float* x = (const float*)d_in[0];
    float* out = (float*)d_out;

    MatPtrs mats;
    for (int i = 0; i < NGROUPS; i++) mats.p[i] = (const float*)d_in[1 + i];

    dim3 grid(NCOLS / BN, (320 + BM - 1) / BM, NGROUPS);  // 84 x 10 x 15
    dim3 block(256);
    bdiag_gemm_kernel<<<grid, block>>>(x, out, mats);
}

// round 3
// speedup vs baseline: 3.1009x; 3.1009x over previous
#include <cuda_runtime.h>
#include <cuda_bf16.h>
#include <cstdint>
#include <cstddef>

// Block-diagonal batched GEMM via warp-level bf16 HMMA (mma.sync), hi/lo split
// for fp32-grade accuracy. compute_103-safe (no tcgen05 / no 'a' features).
//   out[start_g + r, c] = sum_h M_g[r,h] * x[start_g + h, c],  c in [0,10752)

#define NGROUPS 15
#define NCOLS   10752
#define NTILES  37

__constant__ int c_g[NGROUPS]     = {64,128,256,96,160,224,192,288,320,112,80,48,32,16,32};
__constant__ int c_start[NGROUPS] = {0,64,192,448,544,704,928,1120,1408,1728,1840,1920,1968,2000,2016};
__constant__ int c_kpad[NGROUPS]  = {64,128,256,128,192,256,192,320,320,128,128,64,64,64,64};
__constant__ int c_aoff[NGROUPS]  = {0,4096,20480,86016,98304,129024,186368,223232,315392,417792,432128,442368,445440,447488,448512};
__constant__ int c_tileg[NTILES]  = {0, 1,1, 2,2,2,2, 3,3, 4,4,4, 5,5,5,5, 6,6,6,
                                     7,7,7,7,7, 8,8,8,8,8, 9,9, 10,10, 11, 12, 13, 14};
__constant__ int c_tiler[NTILES]  = {0, 0,64, 0,64,128,192, 0,64, 0,64,128, 0,64,128,192, 0,64,128,
                                     0,64,128,192,256, 0,64,128,192,256, 0,64, 0,64, 0, 0, 0, 0};

// bf16 hi/lo split of the block matrices, K padded to 64-multiples, zero-filled.
__device__ __nv_bfloat16 g_Ah[450560];
__device__ __nv_bfloat16 g_Al[450560];

struct MatPtrs { const float* p[NGROUPS]; };

// ---------------- PTX helpers (all compute_103-legal) ----------------
__device__ __forceinline__ uint32_t smem_u32(const void* p) {
    uint32_t a;
    asm("{ .reg .u64 t; cvta.to.shared.u64 t, %1; cvt.u32.u64 %0, t; }" : "=r"(a) : "l"(p));
    return a;
}
__device__ __forceinline__ void ldsm_x4(uint32_t* r, uint32_t addr) {
    asm volatile("ldmatrix.sync.aligned.m8n8.x4.shared.b16 {%0,%1,%2,%3}, [%4];"
        : "=r"(r[0]), "=r"(r[1]), "=r"(r[2]), "=r"(r[3]) : "r"(addr));
}
__device__ __forceinline__ void ldsm_x4_t(uint32_t* r, uint32_t addr) {
    asm volatile("ldmatrix.sync.aligned.m8n8.x4.trans.shared.b16 {%0,%1,%2,%3}, [%4];"
        : "=r"(r[0]), "=r"(r[1]), "=r"(r[2]), "=r"(r[3]) : "r"(addr));
}
__device__ __forceinline__ void mma_bf16(float* c, const uint32_t* a, uint32_t b0, uint32_t b1) {
    asm volatile("mma.sync.aligned.m16n8k16.row.col.f32.bf16.bf16.f32 "
        "{%0,%1,%2,%3}, {%4,%5,%6,%7}, {%8,%9}, {%0,%1,%2,%3};"
        : "+f"(c[0]), "+f"(c[1]), "+f"(c[2]), "+f"(c[3])
        : "r"(a[0]), "r"(a[1]), "r"(a[2]), "r"(a[3]), "r"(b0), "r"(b1));
}

// ---------------- pre-kernel: split mats into bf16 hi/lo (K zero-padded) ----------------
__global__ void conv_mats_kernel(MatPtrs mats) {
    const int g   = blockIdx.y;
    const int G   = c_g[g];
    const int Kp  = c_kpad[g];
    const int n   = G * Kp;
    const int idx = blockIdx.x * 256 + threadIdx.x;
    if (idx >= n) return;
    const int m = idx / Kp;
    const int k = idx - m * Kp;
    float v = (k < G) ? mats.p[g][m * G + k] : 0.0f;
    __nv_bfloat16 h = __float2bfloat16(v);
    __nv_bfloat16 l = __float2bfloat16(v - __bfloat162float(h));
    g_Ah[c_aoff[g] + idx] = h;
    g_Al[c_aoff[g] + idx] = l;
}

// ---------------- main HMMA kernel ----------------
#define APITCH 40    // 32 k + 8 pad (bf16 elems) -> 80B rows, ldmatrix conflict-free
#define BPITCH 136   // 128 n + 8 pad (bf16 elems) -> 272B rows, conflict-free

__global__ __launch_bounds__(256, 2)
void bdiag_hmma_kernel(const float* __restrict__ x, float* __restrict__ out)
{
    __shared__ __nv_bfloat16 sAh[64 * APITCH];
    __shared__ __nv_bfloat16 sAl[64 * APITCH];
    __shared__ __nv_bfloat16 sBh[32 * BPITCH];
    __shared__ __nv_bfloat16 sBl[32 * BPITCH];

    const int tid    = threadIdx.x;
    const int lane   = tid & 31;
    const int wid    = tid >> 5;
    const int warp_m = wid & 1;    // 2 warps over M
    const int warp_n = wid >> 1;   // 4 warps over N

    const int tile  = blockIdx.y;
    const int grp   = c_tileg[tile];
    const int K     = c_g[grp];
    const int Kpad  = c_kpad[grp];
    const int row0  = c_tiler[tile];
    const int col0  = blockIdx.x * 128;
    const int xbase = c_start[grp];

    const __nv_bfloat16* __restrict__ Ahg = g_Ah + c_aoff[grp];
    const __nv_bfloat16* __restrict__ Alg = g_Al + c_aoff[grp];

    const uint32_t sAh_b = smem_u32(sAh);
    const uint32_t sAl_b = smem_u32(sAl);
    const uint32_t sBh_b = smem_u32(sBh);
    const uint32_t sBl_b = smem_u32(sBl);

    float acc[2][4][4];
    #pragma unroll
    for (int mi = 0; mi < 2; mi++)
        #pragma unroll
        for (int ni = 0; ni < 4; ni++)
            #pragma unroll
            for (int q = 0; q < 4; q++) acc[mi][ni][q] = 0.0f;

    // ldmatrix per-thread element offsets
    const int lr = lane & 15;      // row within 16
    const int lc = lane >> 4;      // 0/1 -> k (A) or n (B) 8-offset

    const int nch = Kpad >> 5;     // K chunks of 32
    for (int ch = 0; ch < nch; ch++) {
        const int kc0 = ch << 5;

        __syncthreads();  // previous compute done before smem overwrite

        // --- A hi/lo: 64 rows x 32 k bf16, one uint4 (8 bf16) per thread per matrix
        {
            const int m   = tid >> 2;
            const int seg = tid & 3;
            uint4 vh = make_uint4(0, 0, 0, 0), vl = vh;
            const int gr = row0 + m;
            if (gr < K) {
                const size_t off = (size_t)gr * Kpad + kc0 + seg * 8;
                vh = *reinterpret_cast<const uint4*>(Ahg + off);
                vl = *reinterpret_cast<const uint4*>(Alg + off);
            }
            *reinterpret_cast<uint4*>(sAh + m * APITCH + seg * 8) = vh;
            *reinterpret_cast<uint4*>(sAl + m * APITCH + seg * 8) = vl;
        }

        // --- B hi/lo: x chunk [32 k][128 n] fp32 -> bf16 split, k-major smem
        #pragma unroll
        for (int i = 0; i < 4; i++) {
            const int idx = tid + i * 256;  // 1024 float4 slots
            const int k   = idx >> 5;
            const int c4  = idx & 31;
            float4 v = make_float4(0.f, 0.f, 0.f, 0.f);
            if (kc0 + k < K)
                v = *reinterpret_cast<const float4*>(
                        x + (size_t)(xbase + kc0 + k) * NCOLS + col0 + c4 * 4);
            __nv_bfloat162 h01 = __floats2bfloat162_rn(v.x, v.y);
            __nv_bfloat162 h23 = __floats2bfloat162_rn(v.z, v.w);
            __nv_bfloat162 l01 = __floats2bfloat162_rn(
                v.x - __bfloat162float(__low2bfloat16(h01)),
                v.y - __bfloat162float(__high2bfloat16(h01)));
            __nv_bfloat162 l23 = __floats2bfloat162_rn(
                v.z - __bfloat162float(__low2bfloat16(h23)),
                v.w - __bfloat162float(__high2bfloat16(h23)));
            uint2 uh, ul;
            uh.x = *reinterpret_cast<uint32_t*>(&h01);
            uh.y = *reinterpret_cast<uint32_t*>(&h23);
            ul.x = *reinterpret_cast<uint32_t*>(&l01);
            ul.y = *reinterpret_cast<uint32_t*>(&l23);
            *reinterpret_cast<uint2*>(sBh + k * BPITCH + c4 * 4) = uh;
            *reinterpret_cast<uint2*>(sBl + k * BPITCH + c4 * 4) = ul;
        }

        __syncthreads();

        // --- compute: 2 k16-steps, 3-product bf16 split
        #pragma unroll
        for (int ks = 0; ks < 2; ks++) {
            uint32_t ah[2][4], al[2][4];
            #pragma unroll
            for (int mi = 0; mi < 2; mi++) {
                const uint32_t aoff =
                    ((warp_m * 32 + mi * 16 + lr) * APITCH + ks * 16 + lc * 8) * 2;
                ldsm_x4(ah[mi], sAh_b + aoff);
                ldsm_x4(al[mi], sAl_b + aoff);
            }
            uint32_t bh[2][4], bl[2][4];
            #pragma unroll
            for (int p = 0; p < 2; p++) {
                const uint32_t boff =
                    ((ks * 16 + lr) * BPITCH + warp_n * 32 + p * 16 + lc * 8) * 2;
                ldsm_x4_t(bh[p], sBh_b + boff);
                ldsm_x4_t(bl[p], sBl_b + boff);
            }
            #pragma unroll
            for (int mi = 0; mi < 2; mi++)
                #pragma unroll
                for (int ni = 0; ni < 4; ni++) {
                    const int p = ni >> 1, s = (ni & 1) * 2;
                    mma_bf16(acc[mi][ni], ah[mi], bh[p][s], bh[p][s + 1]);
                    mma_bf16(acc[mi][ni], ah[mi], bl[p][s], bl[p][s + 1]);
                    mma_bf16(acc[mi][ni], al[mi], bh[p][s], bh[p][s + 1]);
                }
        }
    }

    // --- epilogue: masked float2 stores straight from fragments
    const int rbase = row0 + warp_m * 32 + (lane >> 2);
    const int cb    = col0 + warp_n * 32 + (lane & 3) * 2;
    #pragma unroll
    for (int mi = 0; mi < 2; mi++) {
        #pragma unroll
        for (int half = 0; half < 2; half++) {
            const int row = rbase + mi * 16 + half * 8;
            if (row < K) {
                float* dst = out + (size_t)(xbase + row) * NCOLS + cb;
                #pragma unroll
                for (int ni = 0; ni < 4; ni++) {
                    float2 v = make_float2(acc[mi][ni][half * 2],
                                           acc[mi][ni][half * 2 + 1]);
                    *reinterpret_cast<float2*>(dst + ni * 8) = v;
                }
            }
        }
    }
}

extern "C" void kernel_launch(void* const* d_in, const int* in_sizes, int n_in,
                              void* d_out, int out_size)
{
    const float* x = (const float*)d_in[0];
    float* out = (float*)d_out;

    MatPtrs mats;
    for (int i = 0; i < NGROUPS; i++) mats.p[i] = (const float*)d_in[1 + i];

    conv_mats_kernel<<<dim3(400, NGROUPS), 256>>>(mats);
    bdiag_hmma_kernel<<<dim3(NCOLS / 128, NTILES), 256>>>(x, out);
}